// round 2
// baseline (speedup 1.0000x reference)
#include <cuda_runtime.h>

#define PI_D 3.141592653589793238462643383279502884

__constant__ double C_FACTD[11] = {1.,1.,2.,6.,24.,120.,720.,5040.,40320.,362880.,3628800.};

__device__ float  g_w_in[20], g_w_l1[12], g_w_l2[6];
__device__ float2 g_e20[20], g_e12[12], g_e6[6];
__device__ float  g_DS2 [1320];    // [l6][k20][m'+5]
__device__ float  g_TD1 [8712];    // [l6][k12][m'+5][p'+5] *(2l+1)
__device__ float  g_DSO3[900];     // [l3][k12][m2+2][p2+2] *w
__device__ float  g_TD2 [450];     // [l3][k6][m2+2][p2+2] *(2l+1)
__device__ float2 g_PSI1[1584];    // [l6][g24][m'+5]
__device__ float2 g_PSI2[10800];   // [l3][g144][m+2][p+2]
__device__ float2 g_CY1 [528];     // [l6][o8][p'+5]
__device__ float2 g_CY2 [9600];    // [l3][f8][o16][p2+2][k2+2]
__device__ float  g_feat[2048*16];

__device__ double wig_dd(int l, int mp, int m, double beta) {
    if (mp < -l || mp > l || m < -l || m > l) return 0.0;
    double c = cos(0.5*beta), s = sin(0.5*beta);
    int k0 = max(0, m - mp), k1 = min(l + m, l - mp);
    if (k1 < k0) return 0.0;
    double pre = sqrt(C_FACTD[l+mp]*C_FACTD[l-mp]*C_FACTD[l+m]*C_FACTD[l-m]);
    double acc = 0.0;
    for (int k = k0; k <= k1; k++) {
        double t = pre/(C_FACTD[l+m-k]*C_FACTD[k]*C_FACTD[mp-m+k]*C_FACTD[l-mp-k]);
        int ec = 2*l - 2*k + m - mp, es = mp - m + 2*k;
        double pc = 1.0, ps = 1.0;
        for (int i = 0; i < ec; i++) pc *= c;
        for (int i = 0; i < es; i++) ps *= s;
        t *= pc*ps;
        acc += ((mp - m + k) & 1) ? -t : t;
    }
    return acc;
}

__global__ void k_quad() {
    int t = threadIdx.x;
    if (t < 20) {
        double beta = PI_D*(2*t+1)/40.0, ss = 0.0;
        for (int j = 0; j < 10; j++) ss += sin((2*j+1)*beta)/(2*j+1);
        g_w_in[t] = (float)((2.0/10.0)*sin(beta)*ss);
        double a = 2.0*PI_D*t/20.0;
        g_e20[t] = make_float2((float)cos(a), (float)sin(a));
    }
    if (t < 12) {
        double beta = PI_D*(2*t+1)/24.0, ss = 0.0;
        for (int j = 0; j < 6; j++) ss += sin((2*j+1)*beta)/(2*j+1);
        g_w_l1[t] = (float)((2.0/6.0)*sin(beta)*ss);
        double a = 2.0*PI_D*t/12.0;
        g_e12[t] = make_float2((float)cos(a), (float)sin(a));
    }
    if (t < 6) {
        double beta = PI_D*(2*t+1)/12.0, ss = 0.0;
        for (int j = 0; j < 3; j++) ss += sin((2*j+1)*beta)/(2*j+1);
        g_w_l2[t] = (float)((2.0/3.0)*sin(beta)*ss);
        double a = 2.0*PI_D*t/6.0;
        g_e6[t] = make_float2((float)cos(a), (float)sin(a));
    }
}

__global__ void k_tables() {
    const int N0=1320, N1=8712, N2=900, N3=450, N4=1584, N5=10800;
    int stride = gridDim.x * blockDim.x;
    for (int e = blockIdx.x*blockDim.x + threadIdx.x; e < N0+N1+N2+N3+N4+N5; e += stride) {
        int i = e;
        if (i < N0) {
            int j = i%11, k = (i/11)%20, l = i/220;
            double beta = PI_D*(2*k+1)/40.0;
            g_DS2[i] = (float)(wig_dd(l, j-5, 0, beta)) * g_w_in[k];
            continue;
        }
        i -= N0;
        if (i < N1) {
            int j = i%11, mi = (i/11)%11, k = (i/121)%12, l = i/1452;
            double beta = PI_D*(2*k+1)/24.0;
            g_TD1[i] = (float)((2*l+1) * wig_dd(l, mi-5, j-5, beta));
            continue;
        }
        i -= N1;
        if (i < N2) {
            int j = i%5, mi = (i/5)%5, k = (i/25)%12, l = i/300;
            double beta = PI_D*(2*k+1)/24.0;
            g_DSO3[i] = (float)(wig_dd(l, mi-2, j-2, beta)) * g_w_l1[k];
            continue;
        }
        i -= N2;
        if (i < N3) {
            int j = i%5, mi = (i/5)%5, k = (i/25)%6, l = i/150;
            double beta = PI_D*(2*k+1)/12.0;
            g_TD2[i] = (float)((2*l+1) * wig_dd(l, mi-2, j-2, beta));
            continue;
        }
        i -= N3;
        if (i < N4) {
            int j = i%11, g = (i/11)%24, l = i/264;
            int mp = j - 5;
            double b  = (double)(g/8 + 1) * (PI_D/24.0);
            double al = (double)(g%8) * (PI_D/4.0);
            double d  = wig_dd(l, mp, 0, b);
            double ang = -(double)mp * al;
            g_PSI1[i] = make_float2((float)(d*cos(ang)), (float)(d*sin(ang)));
            continue;
        }
        i -= N4;
        {
            int j = i%5, mi = (i/5)%5, g = (i/25)%144, l = i/3600;
            int m = mi - 2, p = j - 2;
            double b  = (double)(g/48 + 1) * (PI_D/24.0);
            double al = (double)((g/6)%8) * (PI_D/4.0);
            double ga = (double)(g%6) * (PI_D/3.0);
            double d  = wig_dd(l, m, p, b);
            double ang = -((double)m*al + (double)p*ga);
            g_PSI2[i] = make_float2((float)(d*cos(ang)), (float)(d*sin(ang)));
        }
    }
}

__global__ void k_weights(const float* __restrict__ w1, const float* __restrict__ w2) {
    const int NC1 = 528, NC2 = 9600;
    int stride = gridDim.x * blockDim.x;
    for (int e = blockIdx.x*blockDim.x + threadIdx.x; e < NC1+NC2; e += stride) {
        if (e < NC1) {
            int j = e%11, o = (e/11)%8, l = e/88;
            float re = 0.f, im = 0.f;
            for (int g = 0; g < 24; g++) {
                float wv = w1[o*24 + g];
                float2 ps = g_PSI1[(l*24 + g)*11 + j];
                re += wv*ps.x; im += wv*ps.y;
            }
            g_CY1[e] = make_float2(re, -im);
        } else {
            int i = e - NC1;
            int k2 = i%5, j2 = (i/5)%5, o = (i/25)%16, f = (i/400)%8, l = i/3200;
            float re = 0.f, im = 0.f;
            for (int g = 0; g < 144; g++) {
                float wv = w2[(f*16 + o)*144 + g];
                float2 ps = g_PSI2[((l*144 + g)*5 + j2)*5 + k2];
                re += wv*ps.x; im += wv*ps.y;
            }
            g_CY2[i] = make_float2(re, -im);
        }
    }
}

__device__ __forceinline__ float2 cfma(float2 a, float2 b, float2 c) {
    c.x += a.x*b.x - a.y*b.y;
    c.y += a.x*b.y + a.y*b.x;
    return c;
}

#define SM_FLOATS (256 + 2*13824)
#define SM_BYTES  (SM_FLOATS*4)

__global__ void __launch_bounds__(512)
k_forward(const float* __restrict__ x, const float* __restrict__ b1,
          const float* __restrict__ b2) {
    extern __shared__ float sm[];
    float2* se20 = (float2*)(sm);        // 20c @ 0
    float2* se12 = (float2*)(sm + 40);   // 12c
    float2* se6  = (float2*)(sm + 64);   // 6c
    float*  sb1  = sm + 76;              // 8
    float*  sb2  = sm + 84;              // 16
    float*  swi  = sm + 100;             // 6
    float2* sXS  = (float2*)(sm + 108);  // 66c
    float*  A    = sm + 256;
    float*  Bb   = sm + 256 + 13824;

    const int tid = threadIdx.x;
    const int n = blockIdx.x;

    if (tid < 20)                se20[tid]     = g_e20[tid];
    if (tid >= 32  && tid < 44)  se12[tid-32]  = g_e12[tid-32];
    if (tid >= 64  && tid < 70)  se6 [tid-64]  = g_e6 [tid-64];
    if (tid >= 96  && tid < 104) sb1 [tid-96]  = b1[tid-96];
    if (tid >= 128 && tid < 144) sb2 [tid-128] = b2[tid-128];
    if (tid >= 160 && tid < 166) swi [tid-160] = g_w_l2[tid-160];

    // Ph0: load x[n] (20x20) into A
    float* sx = A;
    for (int i = tid; i < 400; i += 512) sx[i] = x[n*400 + i];
    __syncthreads();

    // Ph1: alpha analysis Xf[k][m'+5] = sum_a x[k,a] e^{-2pi i m' a/20}  (B)
    float2* Xf = (float2*)Bb;
    for (int it = tid; it < 220; it += 512) {
        int k = it/11, mp = (it%11) - 5;
        float re = 0.f, im = 0.f;
        #pragma unroll
        for (int a = 0; a < 20; a++) {
            int r = (-(mp*a)) % 20; if (r < 0) r += 20;
            float v = sx[k*20 + a];
            re += v*se20[r].x; im += v*se20[r].y;
        }
        Xf[it] = make_float2(re, im);
    }
    __syncthreads();

    // Ph2: XS[l][m'+5] = sum_k DS2 * Xf
    for (int it = tid; it < 66; it += 512) {
        int l = it/11, j = it%11;
        float2 acc = make_float2(0.f, 0.f);
        #pragma unroll
        for (int k = 0; k < 20; k++) {
            float d = g_DS2[(l*20 + k)*11 + j];
            acc.x += d*Xf[k*11 + j].x; acc.y += d*Xf[k*11 + j].y;
        }
        sXS[it] = acc;
    }
    __syncthreads();

    // Ph3: P[l][o][m'(0..5)][p'+5] = XS * CY1   (A)
    float2* P = (float2*)A;
    for (int it = tid; it < 3168; it += 512) {
        int j = it%11, mq = (it/11)%6, o = (it/66)%8, l = it/528;
        float2 xs = sXS[l*11 + mq + 5];
        float2 cy = g_CY1[(l*8 + o)*11 + j];
        P[it] = make_float2(xs.x*cy.x - xs.y*cy.y, xs.x*cy.y + xs.y*cy.x);
    }
    __syncthreads();

    // Ph4: Fh[o][k][m'(0..5)][p'+5] = sum_l TD1 * P   (B)
    float2* Fh = (float2*)Bb;
    for (int it = tid; it < 6336; it += 512) {
        int j = it%11, mq = (it/11)%6, k = (it/66)%12, o = it/792;
        float2 acc = make_float2(0.f, 0.f);
        #pragma unroll
        for (int l = 0; l < 6; l++) {
            float d = g_TD1[((l*12 + k)*11 + (mq+5))*11 + j];
            float2 p = P[((l*8 + o)*6 + mq)*11 + j];
            acc.x += d*p.x; acc.y += d*p.y;
        }
        Fh[it] = acc;
    }
    __syncthreads();

    // Ph5: gamma synthesis G[o][k][m'][g] = sum_p' Fh e^{+2pi i p' g/12}  (A)
    float2* G = (float2*)A;
    for (int it = tid; it < 6912; it += 512) {
        int g = it%12, mq = (it/12)%6, k = (it/72)%12, o = it/864;
        float2 acc = make_float2(0.f, 0.f);
        const float2* fp = Fh + ((o*12 + k)*6 + mq)*11;
        #pragma unroll
        for (int j = 0; j < 11; j++) {
            int r = ((j-5)*g) % 12; if (r < 0) r += 12;
            acc = cfma(fp[j], se12[r], acc);
        }
        G[it] = acc;
    }
    __syncthreads();

    // Ph6: alpha synthesis (Hermitian) + bias + ReLU -> h1[f][k][a][g]  (B)
    float* h1 = Bb;
    for (int it = tid; it < 13824; it += 512) {
        int g = it%12, a = (it/12)%12, k = (it/144)%12, f = it/1728;
        const float2* Gp = G + ((f*12 + k)*6)*12 + g;
        float v = Gp[0].x;
        #pragma unroll
        for (int mq = 1; mq < 6; mq++) {
            float2 w = se12[(mq*a)%12];
            float2 gg = Gp[mq*12];
            v += 2.f*(gg.x*w.x - gg.y*w.y);
        }
        v += sb1[f];
        h1[it] = fmaxf(v, 0.f);
    }
    __syncthreads();

    // Ph7: gamma analysis T[f][k][a][p2=0..2] = sum_g h1 e^{-2pi i p2 g/12} (A)
    float2* T = (float2*)A;
    for (int it = tid; it < 3456; it += 512) {
        int p2 = it%3, a = (it/3)%12, k = (it/36)%12, f = it/432;
        const float* hp = h1 + ((f*12 + k)*12 + a)*12;
        float re = 0.f, im = 0.f;
        #pragma unroll
        for (int g = 0; g < 12; g++) {
            float2 w = se12[(p2*g)%12];
            re += hp[g]*w.x; im -= hp[g]*w.y;
        }
        T[it] = make_float2(re, im);
    }
    __syncthreads();

    // Ph8: alpha analysis F2h[f][k][m2+2][p2+2]   (B)
    float2* F2h = (float2*)Bb;
    for (int it = tid; it < 2400; it += 512) {
        int j2 = it%5, i2 = (it/5)%5, k = (it/25)%12, f = it/300;
        int m2 = i2 - 2, p2 = j2 - 2;
        float2 acc = make_float2(0.f, 0.f);
        #pragma unroll
        for (int a = 0; a < 12; a++) {
            float2 tv;
            if (p2 >= 0) tv = T[((f*12 + k)*12 + a)*3 + p2];
            else { float2 u = T[((f*12 + k)*12 + a)*3 - p2]; tv = make_float2(u.x, -u.y); }
            int r = (-(m2*a)) % 12; if (r < 0) r += 12;
            acc = cfma(tv, se12[r], acc);
        }
        F2h[it] = acc;
    }
    __syncthreads();

    // Ph9: XS2[l][f][m2+2][p2+2] = sum_k F2h * DSO3   (A)
    float2* XS2 = (float2*)A;
    for (int it = tid; it < 600; it += 512) {
        int j2 = it%5, i2 = (it/5)%5, f = (it/25)%8, l = it/200;
        float2 acc = make_float2(0.f, 0.f);
        #pragma unroll
        for (int k = 0; k < 12; k++) {
            float d = g_DSO3[((l*12 + k)*5 + i2)*5 + j2];
            float2 v = F2h[((f*12 + k)*5 + i2)*5 + j2];
            acc.x += d*v.x; acc.y += d*v.y;
        }
        XS2[it] = acc;
    }
    __syncthreads();

    // Ph10: Z2[l][o][m2+2][p2+2] = sum_{f,k2} XS2 * CY2   (B)
    float2* Z2 = (float2*)Bb;
    for (int it = tid; it < 1200; it += 512) {
        int j2 = it%5, i2 = (it/5)%5, o = (it/25)%16, l = it/400;
        float2 acc = make_float2(0.f, 0.f);
        for (int f = 0; f < 8; f++) {
            const float2* xp = XS2 + ((l*8 + f)*5 + i2)*5;
            const float2* cp = g_CY2 + (((l*8 + f)*16 + o)*5 + j2)*5;
            #pragma unroll
            for (int k2 = 0; k2 < 5; k2++) acc = cfma(xp[k2], cp[k2], acc);
        }
        Z2[it] = acc;
    }
    __syncthreads();

    // Ph11a: FH2[o][k][m2(0..2)][p2+2] = sum_l TD2 * Z2   (A)
    float2* FH2 = (float2*)A;
    for (int it = tid; it < 1440; it += 512) {
        int j2 = it%5, mq = (it/5)%3, k = (it/15)%6, o = it/90;
        float2 acc = make_float2(0.f, 0.f);
        #pragma unroll
        for (int l = 0; l < 3; l++) {
            float d = g_TD2[((l*6 + k)*5 + (mq+2))*5 + j2];
            float2 z = Z2[((l*16 + o)*5 + (mq+2))*5 + j2];
            acc.x += d*z.x; acc.y += d*z.y;
        }
        FH2[it] = acc;
    }
    __syncthreads();

    // Ph11b: gamma synthesis G2[o][k][mq][g6] = sum_p2 FH2 e^{+2pi i p2 g/6}  (B)
    float2* G2 = (float2*)Bb;
    for (int it = tid; it < 1728; it += 512) {
        int g = it%6, mq = (it/6)%3, k = (it/18)%6, o = it/108;
        float2 acc = make_float2(0.f, 0.f);
        const float2* fp = FH2 + ((o*6 + k)*3 + mq)*5;
        #pragma unroll
        for (int j2 = 0; j2 < 5; j2++) {
            int r = ((j2-2)*g) % 6; if (r < 0) r += 6;
            acc = cfma(fp[j2], se6[r], acc);
        }
        G2[it] = acc;
    }
    __syncthreads();

    // Ph12: alpha synthesis (Hermitian) + bias + ReLU -> h2[o][k][a][g]  (A)
    float* h2 = A;
    for (int it = tid; it < 3456; it += 512) {
        int g = it%6, a = (it/6)%6, k = (it/36)%6, o = it/216;
        const float2* Gp = G2 + ((o*6 + k)*3)*6 + g;
        float v = Gp[0].x;
        #pragma unroll
        for (int mq = 1; mq < 3; mq++) {
            float2 w = se6[(mq*a)%6];
            float2 gg = Gp[mq*6];
            v += 2.f*(gg.x*w.x - gg.y*w.y);
        }
        v += sb2[o];
        h2[it] = fmaxf(v, 0.f);
    }
    __syncthreads();

    // Ph13: integrate: feat[n][o] = sum_k w_l2[k]/36 * sum_{a,g} h2[o][k][a][g]
    {
        int w = tid >> 5, lane = tid & 31;   // warp w -> output channel o=w
        const float* hp = h2 + w*216;
        float s = 0.f;
        for (int idx = lane; idx < 216; idx += 32)
            s += hp[idx] * swi[idx/36];
        #pragma unroll
        for (int off = 16; off; off >>= 1)
            s += __shfl_down_sync(0xffffffffu, s, off);
        if (lane == 0) g_feat[n*16 + w] = s * (1.f/36.f);
    }
}

__global__ void k_final(const float* __restrict__ w_out,
                        const float* __restrict__ b_out,
                        float* __restrict__ out) {
    __shared__ float sp[512];
    __shared__ float pooled[16];
    int b = blockIdx.x, t = threadIdx.x;
    int o = t & 15, grp = t >> 4;
    float m = -3.4e38f;
    #pragma unroll
    for (int j = 0; j < 16; j++) {
        int p = grp + j*32;
        m = fmaxf(m, g_feat[(b*512 + p)*16 + o]);
    }
    sp[grp*16 + o] = m;
    __syncthreads();
    if (t < 16) {
        float mm = sp[t];
        for (int g = 1; g < 32; g++) mm = fmaxf(mm, sp[g*16 + t]);
        pooled[t] = mm;
    }
    __syncthreads();
    if (t < 10) {
        float acc = b_out[t];
        #pragma unroll
        for (int o2 = 0; o2 < 16; o2++) acc += pooled[o2]*w_out[t*16 + o2];
        out[b*10 + t] = acc;
    }
}

extern "C" void kernel_launch(void* const* d_in, const int* in_sizes, int n_in,
                              void* d_out, int out_size) {
    const float* x     = (const float*)d_in[0];
    const float* w1    = (const float*)d_in[1];
    const float* b1    = (const float*)d_in[2];
    const float* w2    = (const float*)d_in[3];
    const float* b2    = (const float*)d_in[4];
    const float* w_out = (const float*)d_in[5];
    const float* b_out = (const float*)d_in[6];
    float* out = (float*)d_out;

    cudaFuncSetAttribute(k_forward, cudaFuncAttributeMaxDynamicSharedMemorySize, SM_BYTES);

    k_quad<<<1, 32>>>();
    k_tables<<<64, 256>>>();
    k_weights<<<40, 256>>>(w1, w2);
    k_forward<<<2048, 512, SM_BYTES>>>(x, b1, b2);
    k_final<<<4, 512>>>(w_out, b_out, out);
}

// round 3
// speedup vs baseline: 1.8269x; 1.8269x over previous
#include <cuda_runtime.h>

#define PI_D 3.141592653589793238462643383279502884
#define PI_F 3.14159265358979323846f

__constant__ float C_FACTF[11] = {1.f,1.f,2.f,6.f,24.f,120.f,720.f,5040.f,
                                  40320.f,362880.f,3628800.f};

__device__ float  g_w_in[20], g_w_l1[12], g_w_l2[6];
__device__ float2 g_e20[20], g_e12[12], g_e6[6];
__device__ float  g_DS2 [1320];    // [l6][k20][m'+5]
__device__ float  g_TD1 [8712];    // [l6][k12][m'+5][p'+5] *(2l+1)
__device__ float  g_DSO3[900];     // [l3][k12][m2+2][p2+2] *w
__device__ float  g_TD2 [450];     // [l3][k6][m2+2][p2+2] *(2l+1)
__device__ float2 g_PSI1[1584];    // [l6][g24][m'+5]
__device__ float2 g_PSI2[10800];   // [l3][g144][m+2][p+2]
__device__ float2 g_CY1 [528];     // [l6][o8][p'+5]
__device__ float2 g_CY2 [9600];    // [l3][f8][o16][p2+2][k2+2]
__device__ float  g_feat[2048*16];

__device__ float wig_df(int l, int mp, int m, float beta) {
    if (mp < -l || mp > l || m < -l || m > l) return 0.f;
    float c = cosf(0.5f*beta), s = sinf(0.5f*beta);
    int k0 = max(0, m - mp), k1 = min(l + m, l - mp);
    if (k1 < k0) return 0.f;
    float pre = sqrtf(C_FACTF[l+mp]*C_FACTF[l-mp]*C_FACTF[l+m]*C_FACTF[l-m]);
    float acc = 0.f;
    for (int k = k0; k <= k1; k++) {
        float t = pre/(C_FACTF[l+m-k]*C_FACTF[k]*C_FACTF[mp-m+k]*C_FACTF[l-mp-k]);
        int ec = 2*l - 2*k + m - mp, es = mp - m + 2*k;
        float pc = 1.f, ps = 1.f;
        for (int i = 0; i < ec; i++) pc *= c;
        for (int i = 0; i < es; i++) ps *= s;
        acc += (((mp - m + k) & 1) ? -t : t) * pc * ps;
    }
    return acc;
}

__global__ void k_quad() {
    int t = threadIdx.x;
    if (t < 20) {
        double beta = PI_D*(2*t+1)/40.0, ss = 0.0;
        for (int j = 0; j < 10; j++) ss += sin((2*j+1)*beta)/(2*j+1);
        g_w_in[t] = (float)((2.0/10.0)*sin(beta)*ss);
        double a = 2.0*PI_D*t/20.0;
        g_e20[t] = make_float2((float)cos(a), (float)sin(a));
    }
    if (t < 12) {
        double beta = PI_D*(2*t+1)/24.0, ss = 0.0;
        for (int j = 0; j < 6; j++) ss += sin((2*j+1)*beta)/(2*j+1);
        g_w_l1[t] = (float)((2.0/6.0)*sin(beta)*ss);
        double a = 2.0*PI_D*t/12.0;
        g_e12[t] = make_float2((float)cos(a), (float)sin(a));
    }
    if (t < 6) {
        double beta = PI_D*(2*t+1)/12.0, ss = 0.0;
        for (int j = 0; j < 3; j++) ss += sin((2*j+1)*beta)/(2*j+1);
        g_w_l2[t] = (float)((2.0/3.0)*sin(beta)*ss);
        double a = 2.0*PI_D*t/6.0;
        g_e6[t] = make_float2((float)cos(a), (float)sin(a));
    }
}

__global__ void k_tables() {
    const int N0=1320, N1=8712, N2=900, N3=450, N4=1584, N5=10800;
    int stride = gridDim.x * blockDim.x;
    for (int e = blockIdx.x*blockDim.x + threadIdx.x; e < N0+N1+N2+N3+N4+N5; e += stride) {
        int i = e;
        if (i < N0) {
            int j = i%11, k = (i/11)%20, l = i/220;
            float beta = PI_F*(2*k+1)/40.0f;
            g_DS2[i] = wig_df(l, j-5, 0, beta) * g_w_in[k];
            continue;
        }
        i -= N0;
        if (i < N1) {
            int j = i%11, mi = (i/11)%11, k = (i/121)%12, l = i/1452;
            float beta = PI_F*(2*k+1)/24.0f;
            g_TD1[i] = (float)(2*l+1) * wig_df(l, mi-5, j-5, beta);
            continue;
        }
        i -= N1;
        if (i < N2) {
            int j = i%5, mi = (i/5)%5, k = (i/25)%12, l = i/300;
            float beta = PI_F*(2*k+1)/24.0f;
            g_DSO3[i] = wig_df(l, mi-2, j-2, beta) * g_w_l1[k];
            continue;
        }
        i -= N2;
        if (i < N3) {
            int j = i%5, mi = (i/5)%5, k = (i/25)%6, l = i/150;
            float beta = PI_F*(2*k+1)/12.0f;
            g_TD2[i] = (float)(2*l+1) * wig_df(l, mi-2, j-2, beta);
            continue;
        }
        i -= N3;
        if (i < N4) {
            int j = i%11, g = (i/11)%24, l = i/264;
            int mp = j - 5;
            float b  = (float)(g/8 + 1) * (PI_F/24.0f);
            float al = (float)(g%8) * (PI_F/4.0f);
            float d  = wig_df(l, mp, 0, b);
            float ang = -(float)mp * al;
            g_PSI1[i] = make_float2(d*cosf(ang), d*sinf(ang));
            continue;
        }
        i -= N4;
        {
            int j = i%5, mi = (i/5)%5, g = (i/25)%144, l = i/3600;
            int m = mi - 2, p = j - 2;
            float b  = (float)(g/48 + 1) * (PI_F/24.0f);
            float al = (float)((g/6)%8) * (PI_F/4.0f);
            float ga = (float)(g%6) * (PI_F/3.0f);
            float d  = wig_df(l, m, p, b);
            float ang = -((float)m*al + (float)p*ga);
            g_PSI2[i] = make_float2(d*cosf(ang), d*sinf(ang));
        }
    }
}

__global__ void k_weights(const float* __restrict__ w1, const float* __restrict__ w2) {
    const int NC1 = 528, NC2 = 9600;
    int stride = gridDim.x * blockDim.x;
    for (int e = blockIdx.x*blockDim.x + threadIdx.x; e < NC1+NC2; e += stride) {
        if (e < NC1) {
            int j = e%11, o = (e/11)%8, l = e/88;
            float re = 0.f, im = 0.f;
            for (int g = 0; g < 24; g++) {
                float wv = w1[o*24 + g];
                float2 ps = g_PSI1[(l*24 + g)*11 + j];
                re += wv*ps.x; im += wv*ps.y;
            }
            g_CY1[e] = make_float2(re, -im);
        } else {
            int i = e - NC1;
            int k2 = i%5, j2 = (i/5)%5, o = (i/25)%16, f = (i/400)%8, l = i/3200;
            float re = 0.f, im = 0.f;
            for (int g = 0; g < 144; g++) {
                float wv = w2[(f*16 + o)*144 + g];
                float2 ps = g_PSI2[((l*144 + g)*5 + j2)*5 + k2];
                re += wv*ps.x; im += wv*ps.y;
            }
            g_CY2[i] = make_float2(re, -im);
        }
    }
}

__device__ __forceinline__ float2 cfma(float2 a, float2 b, float2 c) {
    c.x += a.x*b.x - a.y*b.y;
    c.y += a.x*b.y + a.y*b.x;
    return c;
}

#define SM_FLOATS (256 + 2*13824)
#define SM_BYTES  (SM_FLOATS*4)

__global__ void __launch_bounds__(512, 2)
k_forward(const float* __restrict__ x, const float* __restrict__ b1,
          const float* __restrict__ b2) {
    extern __shared__ float sm[];
    float2* se20 = (float2*)(sm);        // 20c
    float2* se12 = (float2*)(sm + 40);   // 12c
    float2* se6  = (float2*)(sm + 64);   // 6c
    float*  sb1  = sm + 76;              // 8
    float*  sb2  = sm + 84;              // 16
    float*  swi  = sm + 100;             // 6
    float2* sXS  = (float2*)(sm + 108);  // 66c
    float*  A    = sm + 256;
    float*  Bb   = sm + 256 + 13824;

    const int tid = threadIdx.x;
    const int n = blockIdx.x;

    if (tid < 20)                se20[tid]     = g_e20[tid];
    if (tid >= 32  && tid < 44)  se12[tid-32]  = g_e12[tid-32];
    if (tid >= 64  && tid < 70)  se6 [tid-64]  = g_e6 [tid-64];
    if (tid >= 96  && tid < 104) sb1 [tid-96]  = b1[tid-96];
    if (tid >= 128 && tid < 144) sb2 [tid-128] = b2[tid-128];
    if (tid >= 160 && tid < 166) swi [tid-160] = g_w_l2[tid-160];

    // Ph0: load x[n] (20x20) into A
    float* sx = A;
    for (int i = tid; i < 400; i += 512) sx[i] = x[n*400 + i];
    __syncthreads();

    // Ph1: alpha analysis Xf[k][m'+5] (B). Incremental twiddle index.
    float2* Xf = (float2*)Bb;
    if (tid < 220) {
        int k = tid/11, mp = tid%11 - 5;
        int s = (20 - mp) % 20;           // (-mp) mod 20, mp in [-5,5]
        const float* xp = sx + k*20;
        float re = 0.f, im = 0.f;
        int r = 0;
        #pragma unroll
        for (int a = 0; a < 20; a++) {
            float v = xp[a];
            float2 w = se20[r];
            re += v*w.x; im += v*w.y;
            r += s; if (r >= 20) r -= 20;
        }
        Xf[tid] = make_float2(re, im);
    }
    __syncthreads();

    // Ph2: XS[l][m'+5] = sum_k DS2 * Xf
    if (tid < 66) {
        int l = tid/11, j = tid%11;
        float2 acc = make_float2(0.f, 0.f);
        #pragma unroll
        for (int k = 0; k < 20; k++) {
            float d = g_DS2[(l*20 + k)*11 + j];
            float2 v = Xf[k*11 + j];
            acc.x += d*v.x; acc.y += d*v.y;
        }
        sXS[tid] = acc;
    }
    __syncthreads();

    // Ph3: P[l][o][mq][j] = XS * CY1   (A). One (l,o,mq) tuple per thread.
    float2* P = (float2*)A;
    if (tid < 288) {
        int mq = tid % 6, o = (tid/6) % 8, l = tid/48;
        float2 xs = sXS[l*11 + mq + 5];
        const float2* cy = g_CY1 + (l*8 + o)*11;
        float2* op = P + ((l*8 + o)*6 + mq)*11;
        #pragma unroll
        for (int j = 0; j < 11; j++) {
            float2 c = cy[j];
            op[j] = make_float2(xs.x*c.x - xs.y*c.y, xs.x*c.y + xs.y*c.x);
        }
    }
    __syncthreads();

    // Ph4: Fh[o][k][mq][j] = sum_l TD1 * P   (B). Tuple (o,k,mq), 11-row acc.
    float2* Fh = (float2*)Bb;
    for (int t = tid; t < 576; t += 512) {
        int mq = t % 6, kk = (t/6) % 12, o = t/72;
        float2 acc[11];
        #pragma unroll
        for (int j = 0; j < 11; j++) acc[j] = make_float2(0.f, 0.f);
        #pragma unroll
        for (int l = 0; l < 6; l++) {
            const float* dp = g_TD1 + ((l*12 + kk)*11 + (mq+5))*11;
            const float2* pp = P + ((l*8 + o)*6 + mq)*11;
            #pragma unroll
            for (int j = 0; j < 11; j++) {
                float d = dp[j];
                acc[j].x += d*pp[j].x; acc[j].y += d*pp[j].y;
            }
        }
        float2* op = Fh + ((o*12 + kk)*6 + mq)*11;
        #pragma unroll
        for (int j = 0; j < 11; j++) op[j] = acc[j];
    }
    __syncthreads();

    // Ph5: gamma synthesis G[o][k][mq][g] (A). Compile-time twiddle indices.
    float2* G = (float2*)A;
    for (int t = tid; t < 576; t += 512) {
        int mq = t % 6, kk = (t/6) % 12, o = t/72;
        float2 acc[12];
        #pragma unroll
        for (int g = 0; g < 12; g++) acc[g] = make_float2(0.f, 0.f);
        const float2* fp = Fh + ((o*12 + kk)*6 + mq)*11;
        #pragma unroll
        for (int j = 0; j < 11; j++) {
            float2 f = fp[j];
            #pragma unroll
            for (int g = 0; g < 12; g++) {
                int r = (((j-5)*g) % 12 + 12) % 12;  // constant-folded
                acc[g] = cfma(f, se12[r], acc[g]);
            }
        }
        float2* op = G + ((o*12 + kk)*6 + mq)*12;
        #pragma unroll
        for (int g = 0; g < 12; g++) op[g] = acc[g];
    }
    __syncthreads();

    // Ph6: alpha synthesis (Hermitian) + bias + ReLU -> h1[f][k][a][g] (B)
    float* h1 = Bb;
    for (int t = tid; t < 1152; t += 512) {
        int g = t % 12, kk = (t/12) % 12, f = t/144;
        const float2* Gp = G + (f*12 + kk)*72 + g;
        float v[12];
        float g0 = Gp[0].x;
        #pragma unroll
        for (int a = 0; a < 12; a++) v[a] = g0;
        #pragma unroll
        for (int mq = 1; mq < 6; mq++) {
            float2 gm = Gp[mq*12];
            float gx = 2.f*gm.x, gy = 2.f*gm.y;
            #pragma unroll
            for (int a = 0; a < 12; a++) {
                float2 w = se12[(mq*a) % 12];     // constant-folded
                v[a] += gx*w.x - gy*w.y;
            }
        }
        float bb = sb1[f];
        float* op = h1 + ((f*12 + kk)*12)*12 + g;
        #pragma unroll
        for (int a = 0; a < 12; a++) op[a*12] = fmaxf(v[a] + bb, 0.f);
    }
    __syncthreads();

    // Ph7: gamma analysis T[f][k][a][p2] (A). Compile-time twiddles.
    float2* T = (float2*)A;
    for (int t = tid; t < 1152; t += 512) {
        int a = t % 12, kk = (t/12) % 12, f = t/144;
        const float* hp = h1 + ((f*12 + kk)*12 + a)*12;
        float h[12];
        #pragma unroll
        for (int g = 0; g < 12; g++) h[g] = hp[g];
        float2* op = T + ((f*12 + kk)*12 + a)*3;
        #pragma unroll
        for (int p2 = 0; p2 < 3; p2++) {
            float re = 0.f, im = 0.f;
            #pragma unroll
            for (int g = 0; g < 12; g++) {
                float2 w = se12[(p2*g) % 12];     // constant-folded
                re += h[g]*w.x; im -= h[g]*w.y;
            }
            op[p2] = make_float2(re, im);
        }
    }
    __syncthreads();

    // Ph8: alpha analysis F2h[f][k][m2+2][p2+2] (B). Tuple (f,k,i2), 5 accs.
    float2* F2h = (float2*)Bb;
    if (tid < 480) {
        int i2 = tid % 5, kk = (tid/5) % 12, f = tid/60;
        int m2 = i2 - 2;
        int s = (12 - m2) % 12;               // (-m2) mod 12
        float2 acc[5];
        #pragma unroll
        for (int j = 0; j < 5; j++) acc[j] = make_float2(0.f, 0.f);
        const float2* Tp = T + ((f*12 + kk)*12)*3;
        int r = 0;
        #pragma unroll
        for (int a = 0; a < 12; a++) {
            float2 t0 = Tp[a*3+0], t1 = Tp[a*3+1], t2 = Tp[a*3+2];
            float2 tw = se12[r];
            acc[0] = cfma(make_float2(t2.x, -t2.y), tw, acc[0]);
            acc[1] = cfma(make_float2(t1.x, -t1.y), tw, acc[1]);
            acc[2] = cfma(t0, tw, acc[2]);
            acc[3] = cfma(t1, tw, acc[3]);
            acc[4] = cfma(t2, tw, acc[4]);
            r += s; if (r >= 12) r -= 12;
        }
        float2* op = F2h + ((f*12 + kk)*5 + i2)*5;
        #pragma unroll
        for (int j = 0; j < 5; j++) op[j] = acc[j];
    }
    __syncthreads();

    // Ph9: XS2[l][f][i2][j2] = sum_k F2h * DSO3   (A). Tuple (l,f,i2).
    float2* XS2 = (float2*)A;
    if (tid < 120) {
        int i2 = tid % 5, f = (tid/5) % 8, l = tid/40;
        float2 acc[5];
        #pragma unroll
        for (int j = 0; j < 5; j++) acc[j] = make_float2(0.f, 0.f);
        #pragma unroll
        for (int k = 0; k < 12; k++) {
            const float* dp = g_DSO3 + ((l*12 + k)*5 + i2)*5;
            const float2* vp = F2h + ((f*12 + k)*5 + i2)*5;
            #pragma unroll
            for (int j = 0; j < 5; j++) {
                float d = dp[j];
                acc[j].x += d*vp[j].x; acc[j].y += d*vp[j].y;
            }
        }
        float2* op = XS2 + ((l*8 + f)*5 + i2)*5;
        #pragma unroll
        for (int j = 0; j < 5; j++) op[j] = acc[j];
    }
    __syncthreads();

    // Ph10: Z2[l][o][i2][j2] = sum_{f,k2} XS2 * CY2   (B)
    float2* Z2 = (float2*)Bb;
    for (int t = tid; t < 1200; t += 512) {
        int j2 = t % 5, i2 = (t/5) % 5, o = (t/25) % 16, l = t/400;
        float2 acc = make_float2(0.f, 0.f);
        #pragma unroll
        for (int f = 0; f < 8; f++) {
            const float2* xp = XS2 + ((l*8 + f)*5 + i2)*5;
            const float2* cp = g_CY2 + (((l*8 + f)*16 + o)*5 + j2)*5;
            #pragma unroll
            for (int k2 = 0; k2 < 5; k2++) acc = cfma(xp[k2], cp[k2], acc);
        }
        Z2[((l*16 + o)*5 + i2)*5 + j2] = acc;
    }
    __syncthreads();

    // Ph11a: FH2[o][k][mq][j2] = sum_l TD2 * Z2   (A). Tuple (o,k,mq).
    float2* FH2 = (float2*)A;
    if (tid < 288) {
        int mq = tid % 3, kk = (tid/3) % 6, o = tid/18;
        float2 acc[5];
        #pragma unroll
        for (int j = 0; j < 5; j++) acc[j] = make_float2(0.f, 0.f);
        #pragma unroll
        for (int l = 0; l < 3; l++) {
            const float* dp = g_TD2 + ((l*6 + kk)*5 + (mq+2))*5;
            const float2* zp = Z2 + ((l*16 + o)*5 + (mq+2))*5;
            #pragma unroll
            for (int j = 0; j < 5; j++) {
                float d = dp[j];
                acc[j].x += d*zp[j].x; acc[j].y += d*zp[j].y;
            }
        }
        float2* op = FH2 + ((o*6 + kk)*3 + mq)*5;
        #pragma unroll
        for (int j = 0; j < 5; j++) op[j] = acc[j];
    }
    __syncthreads();

    // Ph11b: gamma synthesis G2[o][k][mq][g6] (B). Compile-time twiddles.
    float2* G2 = (float2*)Bb;
    if (tid < 288) {
        int mq = tid % 3, kk = (tid/3) % 6, o = tid/18;
        float2 acc[6];
        #pragma unroll
        for (int g = 0; g < 6; g++) acc[g] = make_float2(0.f, 0.f);
        const float2* fp = FH2 + ((o*6 + kk)*3 + mq)*5;
        #pragma unroll
        for (int j2 = 0; j2 < 5; j2++) {
            float2 f = fp[j2];
            #pragma unroll
            for (int g = 0; g < 6; g++) {
                int r = (((j2-2)*g) % 6 + 6) % 6;   // constant-folded
                acc[g] = cfma(f, se6[r], acc[g]);
            }
        }
        float2* op = G2 + ((o*6 + kk)*3 + mq)*6;
        #pragma unroll
        for (int g = 0; g < 6; g++) op[g] = acc[g];
    }
    __syncthreads();

    // Ph12: alpha synthesis (Hermitian) + bias + ReLU -> h2[o][k][a][g] (A)
    float* h2 = A;
    for (int t = tid; t < 576; t += 512) {
        int g = t % 6, kk = (t/6) % 6, o = t/36;
        const float2* Gp = G2 + (o*6 + kk)*18 + g;
        float2 g0 = Gp[0], g1 = Gp[6], g2 = Gp[12];
        float g1x = 2.f*g1.x, g1y = 2.f*g1.y, g2x = 2.f*g2.x, g2y = 2.f*g2.y;
        float bb = sb2[o];
        float* op = h2 + ((o*6 + kk)*6)*6 + g;
        #pragma unroll
        for (int a = 0; a < 6; a++) {
            float2 w1v = se6[a % 6];
            float2 w2v = se6[(2*a) % 6];
            float v = g0.x + g1x*w1v.x - g1y*w1v.y + g2x*w2v.x - g2y*w2v.y;
            op[a*6] = fmaxf(v + bb, 0.f);
        }
    }
    __syncthreads();

    // Ph13: integrate: feat[n][o]
    {
        int w = tid >> 5, lane = tid & 31;   // warp w -> channel o=w
        const float* hp = h2 + w*216;
        float s = 0.f;
        for (int idx = lane; idx < 216; idx += 32)
            s += hp[idx] * swi[idx/36];
        #pragma unroll
        for (int off = 16; off; off >>= 1)
            s += __shfl_down_sync(0xffffffffu, s, off);
        if (lane == 0) g_feat[n*16 + w] = s * (1.f/36.f);
    }
}

__global__ void k_final(const float* __restrict__ w_out,
                        const float* __restrict__ b_out,
                        float* __restrict__ out) {
    __shared__ float sp[512];
    __shared__ float pooled[16];
    int b = blockIdx.x, t = threadIdx.x;
    int o = t & 15, grp = t >> 4;
    float m = -3.4e38f;
    #pragma unroll
    for (int j = 0; j < 16; j++) {
        int p = grp + j*32;
        m = fmaxf(m, g_feat[(b*512 + p)*16 + o]);
    }
    sp[grp*16 + o] = m;
    __syncthreads();
    if (t < 16) {
        float mm = sp[t];
        for (int g = 1; g < 32; g++) mm = fmaxf(mm, sp[g*16 + t]);
        pooled[t] = mm;
    }
    __syncthreads();
    if (t < 10) {
        float acc = b_out[t];
        #pragma unroll
        for (int o2 = 0; o2 < 16; o2++) acc += pooled[o2]*w_out[t*16 + o2];
        out[b*10 + t] = acc;
    }
}

extern "C" void kernel_launch(void* const* d_in, const int* in_sizes, int n_in,
                              void* d_out, int out_size) {
    const float* x     = (const float*)d_in[0];
    const float* w1    = (const float*)d_in[1];
    const float* b1    = (const float*)d_in[2];
    const float* w2    = (const float*)d_in[3];
    const float* b2    = (const float*)d_in[4];
    const float* w_out = (const float*)d_in[5];
    const float* b_out = (const float*)d_in[6];
    float* out = (float*)d_out;

    cudaFuncSetAttribute(k_forward, cudaFuncAttributeMaxDynamicSharedMemorySize, SM_BYTES);

    k_quad<<<1, 32>>>();
    k_tables<<<64, 256>>>();
    k_weights<<<40, 256>>>(w1, w2);
    k_forward<<<2048, 512, SM_BYTES>>>(x, b1, b2);
    k_final<<<4, 512>>>(w_out, b_out, out);
}